// round 1
// baseline (speedup 1.0000x reference)
#include <cuda_runtime.h>

typedef unsigned long long ull;

#define NB 16
#define NC 64
#define NN 2048

// Scratch: Z[d][b][c][m] projections (33.5 MB) + ping-pong P buffers (8.4 MB each)
__device__ float g_Z[(size_t)4 * NB * NC * NN];
__device__ float g_P0[(size_t)NB * NC * NN];
__device__ float g_P1[(size_t)NB * NC * NN];

__device__ __forceinline__ ull pack2(float lo, float hi) {
    ull r;
    asm("mov.b64 %0, {%1, %2};" : "=l"(r) : "f"(lo), "f"(hi));
    return r;
}
__device__ __forceinline__ void unpack2(ull v, float& lo, float& hi) {
    asm("mov.b64 {%0, %1}, %2;" : "=f"(lo), "=f"(hi) : "l"(v));
}
__device__ __forceinline__ void fma2(ull& d, ull a, ull b) {
    asm("fma.rn.f32x2 %0, %1, %2, %0;" : "+l"(d) : "l"(a), "l"(b));
}

// ---------------------------------------------------------------------------
// Projection: Z[d][b][c][m] = sum_k U_d[c][k] * x[b][k][m]
//   U_d[c] = W1[d][c] for c<32, W2[d][c-32] for c>=32
// grid (N/128, B, 4), block 256. Thread tile 8c x 4m.
// ---------------------------------------------------------------------------
__global__ __launch_bounds__(256) void proj_kernel(
    const float* __restrict__ x, const float* __restrict__ W1,
    const float* __restrict__ W2)
{
    __shared__ float Ut[64][68];   // Ut[k][c], pad 68 keeps 16B alignment
    __shared__ float xs[64][128];
    const int d = blockIdx.z, b = blockIdx.y, m0 = blockIdx.x * 128;
    const int tid = threadIdx.x;

    for (int i = tid; i < 64 * 64; i += 256) {
        int c = i >> 6, k = i & 63;
        float v = (c < 32) ? W1[(d * 32 + c) * 64 + k]
                           : W2[(d * 32 + (c - 32)) * 64 + k];
        Ut[k][c] = v;
    }
    for (int i = tid; i < 64 * 32; i += 256) {
        int k = i >> 5, j4 = (i & 31) * 4;
        *(float4*)&xs[k][j4] =
            *(const float4*)&x[((size_t)b * NC + k) * NN + m0 + j4];
    }
    __syncthreads();

    const int cg = (tid >> 5) * 8;
    const int mg = (tid & 31) * 4;
    ull acc[8][2];
#pragma unroll
    for (int c = 0; c < 8; c++) { acc[c][0] = 0ull; acc[c][1] = 0ull; }

#pragma unroll 8
    for (int k = 0; k < 64; k++) {
        float4 bv = *(const float4*)&xs[k][mg];
        ull b01 = pack2(bv.x, bv.y), b23 = pack2(bv.z, bv.w);
        float4 a0 = *(const float4*)&Ut[k][cg];
        float4 a1 = *(const float4*)&Ut[k][cg + 4];
        float av[8] = {a0.x, a0.y, a0.z, a0.w, a1.x, a1.y, a1.z, a1.w};
#pragma unroll
        for (int c = 0; c < 8; c++) {
            ull a2 = pack2(av[c], av[c]);
            fma2(acc[c][0], a2, b01);
            fma2(acc[c][1], a2, b23);
        }
    }
    const size_t base = ((size_t)d * NB + b) * NC * (size_t)NN;
#pragma unroll
    for (int c = 0; c < 8; c++) {
        float4 o;
        unpack2(acc[c][0], o.x, o.y);
        unpack2(acc[c][1], o.z, o.w);
        *(float4*)&g_Z[base + (size_t)(cg + c) * NN + m0 + mg] = o;
    }
}

// ---------------------------------------------------------------------------
// One Horner step: out[b] = A[b] (64x2048) @ adj[b] (2048x2048) + Zadd[b]
// step 0: A = Z3, Zadd = Z2, out = P0
// step 1: A = P0, Zadd = Z1, out = P1
// step 2: A = P1, Zadd = Z0, out = d_out with bias (+relu on channels 32..63)
// grid (N/128, B), block 256. Block tile 64c x 128m, BK=32; thread tile 8x4.
// ---------------------------------------------------------------------------
__global__ __launch_bounds__(256) void step_kernel(
    int step, const float* __restrict__ adj,
    const float* __restrict__ bias1, const float* __restrict__ bias2,
    float* __restrict__ d_out)
{
    const size_t CH = (size_t)NB * NC * NN;
    const float* A   = (step == 0) ? (g_Z + 3 * CH) : (step == 1 ? g_P0 : g_P1);
    const float* Zad = g_Z + (size_t)(2 - step) * CH;
    float* out = (step == 2) ? d_out : (step == 0 ? g_P0 : g_P1);

    __shared__ float As[32][68];    // As[k][c], transposed, pad 68 (16B aligned)
    __shared__ float Bs[32][128];   // Bs[k][m]
    const int b  = blockIdx.y;
    const int m0 = blockIdx.x * 128;
    const int tid = threadIdx.x;
    const float* Ab = A   + (size_t)b * NC * NN;
    const float* Jb = adj + (size_t)b * NN * NN;

    const int cg = (tid >> 5) * 8;   // channel group base
    const int mg = (tid & 31) * 4;   // m offset within tile
    ull acc[8][2];
#pragma unroll
    for (int c = 0; c < 8; c++) { acc[c][0] = 0ull; acc[c][1] = 0ull; }

    const int lc = tid >> 3;         // 0..31 (A-load row)
    const int lk = (tid & 7) * 4;    // 0,4,...,28 (A-load k)

    for (int kt = 0; kt < NN; kt += 32) {
        // A tile: 64 rows (c) x 32 (k), stored transposed As[k][c]
        float4 v0 = *(const float4*)&Ab[(size_t)lc * NN + kt + lk];
        float4 v1 = *(const float4*)&Ab[(size_t)(lc + 32) * NN + kt + lk];
        As[lk + 0][lc] = v0.x; As[lk + 1][lc] = v0.y;
        As[lk + 2][lc] = v0.z; As[lk + 3][lc] = v0.w;
        As[lk + 0][lc + 32] = v1.x; As[lk + 1][lc + 32] = v1.y;
        As[lk + 2][lc + 32] = v1.z; As[lk + 3][lc + 32] = v1.w;
        // B tile: 32 rows (k) x 128 (m), fully coalesced float4
#pragma unroll
        for (int r = 0; r < 4; r++) {
            int idx = tid + r * 256;
            int k = idx >> 5;
            int j4 = (idx & 31) * 4;
            *(float4*)&Bs[k][j4] =
                *(const float4*)&Jb[(size_t)(kt + k) * NN + m0 + j4];
        }
        __syncthreads();
#pragma unroll 8
        for (int k = 0; k < 32; k++) {
            float4 bv = *(const float4*)&Bs[k][mg];
            ull b01 = pack2(bv.x, bv.y), b23 = pack2(bv.z, bv.w);
            float4 a0 = *(const float4*)&As[k][cg];     // broadcast reads
            float4 a1 = *(const float4*)&As[k][cg + 4];
            float av[8] = {a0.x, a0.y, a0.z, a0.w, a1.x, a1.y, a1.z, a1.w};
#pragma unroll
            for (int c = 0; c < 8; c++) {
                ull a2 = pack2(av[c], av[c]);
                fma2(acc[c][0], a2, b01);
                fma2(acc[c][1], a2, b23);
            }
        }
        __syncthreads();
    }

    const size_t ob = (size_t)b * NC * NN;
#pragma unroll
    for (int c = 0; c < 8; c++) {
        const int cc = cg + c;
        float4 z = *(const float4*)&Zad[ob + (size_t)cc * NN + m0 + mg];
        float4 o;
        unpack2(acc[c][0], o.x, o.y);
        unpack2(acc[c][1], o.z, o.w);
        o.x += z.x; o.y += z.y; o.z += z.z; o.w += z.w;
        if (step == 2) {
            if (cc < 32) {
                float bb = bias1[cc];
                o.x += bb; o.y += bb; o.z += bb; o.w += bb;
            } else {
                float bb = bias2[cc - 32];
                o.x = fmaxf(o.x + bb, 0.f);
                o.y = fmaxf(o.y + bb, 0.f);
                o.z = fmaxf(o.z + bb, 0.f);
                o.w = fmaxf(o.w + bb, 0.f);
            }
        }
        *(float4*)&out[ob + (size_t)cc * NN + m0 + mg] = o;
    }
}

extern "C" void kernel_launch(void* const* d_in, const int* in_sizes, int n_in,
                              void* d_out, int out_size) {
    (void)in_sizes; (void)n_in; (void)out_size;
    const float* adj = (const float*)d_in[0];
    const float* x   = (const float*)d_in[1];
    const float* W1  = (const float*)d_in[2];
    const float* b1  = (const float*)d_in[3];
    const float* W2  = (const float*)d_in[4];
    const float* b2  = (const float*)d_in[5];
    float* out = (float*)d_out;

    dim3 gp(NN / 128, NB, 4);
    proj_kernel<<<gp, 256>>>(x, W1, W2);

    dim3 gs(NN / 128, NB);
    step_kernel<<<gs, 256>>>(0, adj, b1, b2, out);
    step_kernel<<<gs, 256>>>(1, adj, b1, b2, out);
    step_kernel<<<gs, 256>>>(2, adj, b1, b2, out);
}

// round 4
// speedup vs baseline: 2.1726x; 2.1726x over previous
#include <cuda_runtime.h>
#include <cuda_bf16.h>
#include <cstdint>

typedef unsigned long long ull;

#define NB 16
#define NC 64
#define NN 2048
#define MT 128              // node tile per CTA
#define KC 32               // K chunk
#define NCHUNK (NN / KC)

// smem layout per buffer (bytes): AHI 0..8K, ALO 8K..16K, PHI 16K..20K, PLO 20K..24K
#define BUF_STRIDE 24576
#define OFF_ALO 8192
#define OFF_PHI 16384
#define OFF_PLO 20480

__device__ float g_Z[(size_t)4 * NB * NC * NN];
__device__ float g_P0[(size_t)NB * NC * NN];
__device__ float g_P1[(size_t)NB * NC * NN];

// ---------------------------------------------------------------- helpers ---
__device__ __forceinline__ uint32_t smem_u32(const void* p) {
    uint32_t a;
    asm("{ .reg .u64 t; cvta.to.shared.u64 t, %1; cvt.u32.u64 %0, t; }"
        : "=r"(a) : "l"(p));
    return a;
}
__device__ __forceinline__ void sts128(uint32_t a, uint32_t v0, uint32_t v1,
                                       uint32_t v2, uint32_t v3) {
    asm volatile("st.shared.v4.b32 [%0], {%1, %2, %3, %4};"
                 :: "r"(a), "r"(v0), "r"(v1), "r"(v2), "r"(v3) : "memory");
}
__device__ __forceinline__ void ldsm4(uint32_t* r, uint32_t addr) {
    asm volatile("ldmatrix.sync.aligned.m8n8.x4.shared.b16 {%0,%1,%2,%3}, [%4];"
                 : "=r"(r[0]), "=r"(r[1]), "=r"(r[2]), "=r"(r[3]) : "r"(addr));
}
__device__ __forceinline__ void mma16816(float* d, const uint32_t* a,
                                         uint32_t b0, uint32_t b1) {
    asm volatile(
        "mma.sync.aligned.m16n8k16.row.col.f32.bf16.bf16.f32 "
        "{%0,%1,%2,%3}, {%4,%5,%6,%7}, {%8,%9}, {%0,%1,%2,%3};"
        : "+f"(d[0]), "+f"(d[1]), "+f"(d[2]), "+f"(d[3])
        : "r"(a[0]), "r"(a[1]), "r"(a[2]), "r"(a[3]), "r"(b0), "r"(b1));
}
// split two fp32 into bf16x2 hi + bf16x2 lo (low half = first value)
__device__ __forceinline__ void splitpair(float x, float y, uint32_t& hi, uint32_t& lo) {
    __nv_bfloat162 h = __floats2bfloat162_rn(x, y);
    float2 hf = __bfloat1622float2(h);
    __nv_bfloat162 l = __floats2bfloat162_rn(x - hf.x, y - hf.y);
    hi = *reinterpret_cast<uint32_t*>(&h);
    lo = *reinterpret_cast<uint32_t*>(&l);
}

// ----------------------------------------------------------------- FFMA2 ----
__device__ __forceinline__ ull pack2(float lo, float hi) {
    ull r; asm("mov.b64 %0, {%1, %2};" : "=l"(r) : "f"(lo), "f"(hi)); return r;
}
__device__ __forceinline__ void unpack2(ull v, float& lo, float& hi) {
    asm("mov.b64 {%0, %1}, %2;" : "=f"(lo), "=f"(hi) : "l"(v));
}
__device__ __forceinline__ void fma2(ull& d, ull a, ull b) {
    asm("fma.rn.f32x2 %0, %1, %2, %0;" : "+l"(d) : "l"(a), "l"(b));
}

// ---------------------------------------------------------------------------
// Projection: Z[d][b][c][m] = sum_k U_d[c][k] * x[b][k][m]  (fp32, FFMA2)
// ---------------------------------------------------------------------------
__global__ __launch_bounds__(256) void proj_kernel(
    const float* __restrict__ x, const float* __restrict__ W1,
    const float* __restrict__ W2)
{
    __shared__ float Ut[64][68];
    __shared__ float xs[64][128];
    const int d = blockIdx.z, b = blockIdx.y, m0 = blockIdx.x * 128;
    const int tid = threadIdx.x;

    for (int i = tid; i < 64 * 64; i += 256) {
        int c = i >> 6, k = i & 63;
        Ut[k][c] = (c < 32) ? W1[(d * 32 + c) * 64 + k]
                            : W2[(d * 32 + (c - 32)) * 64 + k];
    }
    for (int i = tid; i < 64 * 32; i += 256) {
        int k = i >> 5, j4 = (i & 31) * 4;
        *(float4*)&xs[k][j4] = *(const float4*)&x[((size_t)b * NC + k) * NN + m0 + j4];
    }
    __syncthreads();

    const int cg = (tid >> 5) * 8;
    const int mg = (tid & 31) * 4;
    ull acc[8][2];
#pragma unroll
    for (int c = 0; c < 8; c++) { acc[c][0] = 0ull; acc[c][1] = 0ull; }

#pragma unroll 8
    for (int k = 0; k < 64; k++) {
        float4 bv = *(const float4*)&xs[k][mg];
        ull b01 = pack2(bv.x, bv.y), b23 = pack2(bv.z, bv.w);
        float4 a0 = *(const float4*)&Ut[k][cg];
        float4 a1 = *(const float4*)&Ut[k][cg + 4];
        float av[8] = {a0.x, a0.y, a0.z, a0.w, a1.x, a1.y, a1.z, a1.w};
#pragma unroll
        for (int c = 0; c < 8; c++) {
            ull a2 = pack2(av[c], av[c]);
            fma2(acc[c][0], a2, b01);
            fma2(acc[c][1], a2, b23);
        }
    }
    const size_t base = ((size_t)d * NB + b) * NC * (size_t)NN;
#pragma unroll
    for (int c = 0; c < 8; c++) {
        float4 o;
        unpack2(acc[c][0], o.x, o.y);
        unpack2(acc[c][1], o.z, o.w);
        *(float4*)&g_Z[base + (size_t)(cg + c) * NN + m0 + mg] = o;
    }
}

// ---------------------------------------------------------------------------
// HMMA Horner step: D[c][m] = sum_k P[c][k]*adj[k][m] (+Z, +bias/relu last).
// A = P tile [c][k] K-major, B = adjT tile [m][k] K-major, split-bf16 x3.
// grid (16 m-tiles, 16 batches), 256 thr, 2 CTAs/SM, double-buffered smem.
// ---------------------------------------------------------------------------
__global__ void __launch_bounds__(256, 2) hmma_step_kernel(
    int step, const float* __restrict__ adj,
    const float* __restrict__ bias1, const float* __restrict__ bias2,
    float* __restrict__ d_out)
{
    const size_t CH = (size_t)NB * NC * NN;
    const float* Bsrc = (step == 0) ? (g_Z + 3 * CH) : (step == 1 ? g_P0 : g_P1);
    const float* Zad  = g_Z + (size_t)(2 - step) * CH;
    float* Pout = (step == 2) ? d_out : (step == 0 ? g_P0 : g_P1);

    extern __shared__ char dynsm[];
    const uint32_t sbase = (smem_u32(dynsm) + 1023u) & ~1023u;

    const int tid = threadIdx.x, warp = tid >> 5, lane = tid & 31;
    const int b = blockIdx.y, m0 = blockIdx.x * MT;
    const float* Jm = adj + (size_t)b * NN * NN + m0;
    const float* Pb = Bsrc + (size_t)b * NC * NN;

    // ---- load/store duty mapping ----
    // adj: thread handles m = tid&127, 16 k's starting at (tid>>7)*16
    const int amld = tid & 127;
    const int akb  = (tid >> 7) * 16;
    const float* aptr = Jm + (size_t)akb * NN + amld;
    // two 16B chunks at kbytes akb*2 and akb*2+16 within row amld (64B rows)
    const uint32_t axor = (uint32_t)((amld << 3) & 0x30);
    const uint32_t relA0 = (uint32_t)(amld * 64) + (((uint32_t)(akb * 2)) ^ axor);
    const uint32_t relA1 = (uint32_t)(amld * 64) + (((uint32_t)(akb * 2 + 16)) ^ axor);
    // P: thread handles c = tid>>2, 8 k's starting at (tid&3)*8
    const int pc = tid >> 2, pk = (tid & 3) * 8;
    const float* pptr = Pb + (size_t)pc * NN + pk;
    const uint32_t pxor = (uint32_t)((pc << 3) & 0x30);
    const uint32_t relP = (uint32_t)(pc * 64) + (((uint32_t)(pk * 2)) ^ pxor);

    // ---- compute mapping ----
    const int cb = (warp >> 2) * 32;      // channel base (0 or 32)
    const int nb = (warp & 3) * 32;       // node base within tile
    const int lrow = lane & 15;
    const uint32_t lkb = (uint32_t)((lane >> 4) * 16);

    float acc[2][4][4];
#pragma unroll
    for (int mt = 0; mt < 2; mt++)
#pragma unroll
        for (int nt = 0; nt < 4; nt++)
#pragma unroll
            for (int i = 0; i < 4; i++) acc[mt][nt][i] = 0.f;

    // prefetch chunk 0
    float ra[16]; float4 rp0, rp1;
#pragma unroll
    for (int j = 0; j < 16; j++) ra[j] = aptr[(size_t)j * NN];
    rp0 = *(const float4*)pptr;
    rp1 = *(const float4*)(pptr + 4);

    for (int i = 0; i < NCHUNK; i++) {
        const uint32_t bufo = sbase + (uint32_t)(i & 1) * BUF_STRIDE;
        // ---- store chunk i (split fp32 -> bf16 hi/lo) ----
        {
            uint32_t h[4], l[4];
#pragma unroll
            for (int q = 0; q < 4; q++) splitpair(ra[2*q], ra[2*q+1], h[q], l[q]);
            sts128(bufo + relA0, h[0], h[1], h[2], h[3]);
            sts128(bufo + OFF_ALO + relA0, l[0], l[1], l[2], l[3]);
#pragma unroll
            for (int q = 0; q < 4; q++) splitpair(ra[8+2*q], ra[9+2*q], h[q], l[q]);
            sts128(bufo + relA1, h[0], h[1], h[2], h[3]);
            sts128(bufo + OFF_ALO + relA1, l[0], l[1], l[2], l[3]);
            uint32_t ph[4], pl[4];
            splitpair(rp0.x, rp0.y, ph[0], pl[0]);
            splitpair(rp0.z, rp0.w, ph[1], pl[1]);
            splitpair(rp1.x, rp1.y, ph[2], pl[2]);
            splitpair(rp1.z, rp1.w, ph[3], pl[3]);
            sts128(bufo + OFF_PHI + relP, ph[0], ph[1], ph[2], ph[3]);
            sts128(bufo + OFF_PLO + relP, pl[0], pl[1], pl[2], pl[3]);
        }
        // ---- prefetch chunk i+1 (LDGs in flight during mma) ----
        if (i + 1 < NCHUNK) {
            const float* ap = aptr + (size_t)(i + 1) * KC * NN;
#pragma unroll
            for (int j = 0; j < 16; j++) ra[j] = ap[(size_t)j * NN];
            const float* pp = pptr + (i + 1) * KC;
            rp0 = *(const float4*)pp;
            rp1 = *(const float4*)(pp + 4);
        }
        __syncthreads();
        // ---- compute on buffer i ----
        const uint32_t AHI = bufo, ALO = bufo + OFF_ALO,
                       PHI = bufo + OFF_PHI, PLO = bufo + OFF_PLO;
#pragma unroll
        for (int ks = 0; ks < 2; ks++) {
            const uint32_t kb = lkb + (uint32_t)ks * 32;
            uint32_t ah[2][4], al[2][4], bh[2][4], bl[2][4];
#pragma unroll
            for (int mt = 0; mt < 2; mt++) {
                uint32_t row = (uint32_t)(cb + mt * 16 + lrow);
                uint32_t off = row * 64 + (kb ^ ((row << 3) & 0x30));
                ldsm4(ah[mt], PHI + off);
                ldsm4(al[mt], PLO + off);
            }
#pragma unroll
            for (int g = 0; g < 2; g++) {
                uint32_t row = (uint32_t)(nb + g * 16 + lrow);
                uint32_t off = row * 64 + (kb ^ ((row << 3) & 0x30));
                ldsm4(bh[g], AHI + off);
                ldsm4(bl[g], ALO + off);
            }
#pragma unroll
            for (int mt = 0; mt < 2; mt++)
#pragma unroll
                for (int g = 0; g < 2; g++)
#pragma unroll
                    for (int s = 0; s < 2; s++) {
                        float* d = acc[mt][g * 2 + s];
                        mma16816(d, ah[mt], bh[g][s], bh[g][s + 2]);   // hi*hi
                        mma16816(d, ah[mt], bl[g][s], bl[g][s + 2]);   // hi*lo
                        mma16816(d, al[mt], bh[g][s], bh[g][s + 2]);   // lo*hi
                    }
        }
    }

    // ---- epilogue: D += Z (+bias/relu on step 2), write fp32 ----
    const int r4 = lane >> 2;
    const int c2 = (lane & 3) * 2;
#pragma unroll
    for (int mt = 0; mt < 2; mt++) {
#pragma unroll
        for (int rp = 0; rp < 2; rp++) {
            const int cc = cb + mt * 16 + rp * 8 + r4;
            const float* Zrow = Zad + ((size_t)b * NC + cc) * NN + m0;
            float* Orow = Pout + ((size_t)b * NC + cc) * NN + m0;
            float bv = 0.f; bool rl = false;
            if (step == 2) {
                if (cc < 32) bv = bias1[cc];
                else { bv = bias2[cc - 32]; rl = true; }
            }
#pragma unroll
            for (int nt = 0; nt < 4; nt++) {
                const int m = nb + nt * 8 + c2;
                float2 z = *(const float2*)(Zrow + m);
                float v0 = acc[mt][nt][rp * 2 + 0] + z.x + bv;
                float v1 = acc[mt][nt][rp * 2 + 1] + z.y + bv;
                if (rl) { v0 = fmaxf(v0, 0.f); v1 = fmaxf(v1, 0.f); }
                float2 o; o.x = v0; o.y = v1;
                *(float2*)(Orow + m) = o;
            }
        }
    }
}

// ---------------------------------------------------------------------------
extern "C" void kernel_launch(void* const* d_in, const int* in_sizes, int n_in,
                              void* d_out, int out_size) {
    (void)in_sizes; (void)n_in; (void)out_size;
    const float* adj = (const float*)d_in[0];
    const float* x   = (const float*)d_in[1];
    const float* W1  = (const float*)d_in[2];
    const float* b1  = (const float*)d_in[3];
    const float* W2  = (const float*)d_in[4];
    const float* b2  = (const float*)d_in[5];
    float* out = (float*)d_out;

    const int SMEM = 2 * BUF_STRIDE + 1024;   // 50176
    cudaFuncSetAttribute(hmma_step_kernel,
                         cudaFuncAttributeMaxDynamicSharedMemorySize, SMEM);

    dim3 gp(NN / 128, NB, 4);
    proj_kernel<<<gp, 256>>>(x, W1, W2);

    dim3 gs(NN / MT, NB);
    hmma_step_kernel<<<gs, 256, SMEM>>>(0, adj, b1, b2, out);
    hmma_step_kernel<<<gs, 256, SMEM>>>(1, adj, b1, b2, out);
    hmma_step_kernel<<<gs, 256, SMEM>>>(2, adj, b1, b2, out);
}